// round 10
// baseline (speedup 1.0000x reference)
#include <cuda_runtime.h>
#include <cuda_bf16.h>
#include <cstdint>

// Problem constants
#define B 16
#define S 4096
#define H 768
#define T 2000

#define POOL_CTAS (148 * 8)     // one full resident wave at 32 regs / 256 thr

// Packed per-token descriptor: start | (len << 16). start <= 4000, len in {0,1,2}.
__device__ int g_desc[B * T];

// ---------------------------------------------------------------------------
// Kernel 1: per-batch exclusive prefix sum over T lengths (shuffle scan),
// writing packed (start, len) descriptors. Fires PDL trigger when done.
// ---------------------------------------------------------------------------
__global__ void __launch_bounds__(1024) scan_kernel(const int* __restrict__ lens) {
    const int b    = blockIdx.x;
    const int tid  = threadIdx.x;
    const int lane = tid & 31;
    const int wid  = tid >> 5;

    const int* L = lens + (size_t)b * T;

    const int idx0 = tid * 2;
    int v0 = 0, v1 = 0;
    if (idx0 + 1 < T) {
        int2 v = *(const int2*)(L + idx0);
        v0 = v.x; v1 = v.y;
    } else if (idx0 < T) {
        v0 = L[idx0];
    }
    int tsum = v0 + v1;

    int incl = tsum;
#pragma unroll
    for (int off = 1; off < 32; off <<= 1) {
        int n = __shfl_up_sync(0xffffffffu, incl, off);
        if (lane >= off) incl += n;
    }
    const int excl = incl - tsum;

    __shared__ int warpsums[32];
    if (lane == 31) warpsums[wid] = incl;
    __syncthreads();

    if (wid == 0) {
        int w = warpsums[lane];
        int wi = w;
#pragma unroll
        for (int off = 1; off < 32; off <<= 1) {
            int n = __shfl_up_sync(0xffffffffu, wi, off);
            if (lane >= off) wi += n;
        }
        warpsums[lane] = wi - w;
    }
    __syncthreads();

    const int base = warpsums[wid] + excl;
    if (idx0 + 1 < T) {
        int2 d;
        d.x = base | (v0 << 16);
        d.y = (base + v0) | (v1 << 16);
        *(int2*)(g_desc + (size_t)b * T + idx0) = d;
    } else if (idx0 < T) {
        g_desc[(size_t)b * T + idx0] = base | (v0 << 16);
    }

    __threadfence();
    asm volatile("griddepcontrol.launch_dependents;" ::: "memory");
}

// ---------------------------------------------------------------------------
// Kernel 2: persistent. One full wave of CTAs; each warp grid-strides over
// half-tokens (384 floats each, 3 float4 per lane). One index load per
// half-token; iteration i+1's loads overlap iteration i's stores.
// ---------------------------------------------------------------------------
__global__ void __launch_bounds__(256) pool_kernel(
    const float* __restrict__ hs,      // [B, S, H]
    float*       __restrict__ out)     // [B, T, H]
{
    asm volatile("griddepcontrol.wait;" ::: "memory");

    const int lane   = threadIdx.x & 31;
    const int warp0  = (blockIdx.x * blockDim.x + threadIdx.x) >> 5;
    const int nwarps = POOL_CTAS * 8;            // 9472 warps
    const int NHALF  = B * T * 2;                // 64000 half-tokens

    for (int h = warp0; h < NHALF; h += nwarps) {
        const int tok  = h >> 1;
        const int half = h & 1;

        const int desc  = __ldg(g_desc + tok);
        const int start = desc & 0xFFFF;
        const int len   = desc >> 16;
        const int b     = tok / T;

        const int f4off = half * 96 + lane;      // 96 float4 per half-row
        float4* dst = (float4*)(out + (size_t)tok * H);

        if (len == 0) {
            const float4 z = make_float4(0.f, 0.f, 0.f, 0.f);
#pragma unroll
            for (int k = 0; k < 3; k++) dst[f4off + 32 * k] = z;
            continue;
        }

        // First covered position is 1 + start (1-based positions)
        const size_t row0 = (size_t)b * S + 1 + start;
        const float4* src0 = (const float4*)(hs + row0 * H);

        float4 acc[3];
#pragma unroll
        for (int k = 0; k < 3; k++) acc[k] = src0[f4off + 32 * k];

        if (len == 2) {
            const float4* src1 = src0 + (H / 4);
#pragma unroll
            for (int k = 0; k < 3; k++) {
                float4 v = src1[f4off + 32 * k];
                acc[k].x = (acc[k].x + v.x) * 0.5f;
                acc[k].y = (acc[k].y + v.y) * 0.5f;
                acc[k].z = (acc[k].z + v.z) * 0.5f;
                acc[k].w = (acc[k].w + v.w) * 0.5f;
            }
        }

#pragma unroll
        for (int k = 0; k < 3; k++) dst[f4off + 32 * k] = acc[k];
    }
}

// ---------------------------------------------------------------------------
extern "C" void kernel_launch(void* const* d_in, const int* in_sizes, int n_in,
                              void* d_out, int out_size)
{
    const float* hs   = (const float*)d_in[0];   // [B,S,H] fp32
    const int*   lens = (const int*)d_in[1];     // [B,T] int32
    float*       out  = (float*)d_out;           // [B,T,H] fp32

    (void)in_sizes; (void)n_in; (void)out_size;

    scan_kernel<<<B, 1024>>>(lens);

    cudaLaunchConfig_t cfg = {};
    cfg.gridDim  = dim3(POOL_CTAS, 1, 1);
    cfg.blockDim = dim3(256, 1, 1);
    cfg.dynamicSmemBytes = 0;
    cfg.stream = (cudaStream_t)0;

    cudaLaunchAttribute attrs[1];
    attrs[0].id = cudaLaunchAttributeProgrammaticStreamSerialization;
    attrs[0].val.programmaticStreamSerializationAllowed = 1;
    cfg.attrs = attrs;
    cfg.numAttrs = 1;

    cudaError_t err = cudaLaunchKernelEx(&cfg, pool_kernel, hs, out);
    if (err != cudaSuccess) {
        pool_kernel<<<POOL_CTAS, 256>>>(hs, out);
    }
}

// round 11
// speedup vs baseline: 1.0238x; 1.0238x over previous
#include <cuda_runtime.h>
#include <cuda_bf16.h>
#include <cstdint>

// Problem constants
#define B 16
#define S 4096
#define H 768
#define T 2000

// Packed per-token descriptor: (global source row0) | (len << 20).
// row0 = b*S + 1 + start <= 15*4096 + 4001 = 65441 < 2^20. len in {0,1,2}.
__device__ int g_desc[B * T];

// ---------------------------------------------------------------------------
// Kernel 1: per-batch exclusive prefix sum over T lengths (shuffle scan),
// writing packed (global_row0, len) descriptors.
// ---------------------------------------------------------------------------
__global__ void __launch_bounds__(1024) scan_kernel(const int* __restrict__ lens) {
    const int b    = blockIdx.x;
    const int tid  = threadIdx.x;
    const int lane = tid & 31;
    const int wid  = tid >> 5;

    const int* L = lens + (size_t)b * T;

    const int idx0 = tid * 2;
    int v0 = 0, v1 = 0;
    if (idx0 + 1 < T) {
        int2 v = *(const int2*)(L + idx0);
        v0 = v.x; v1 = v.y;
    } else if (idx0 < T) {
        v0 = L[idx0];
    }
    int tsum = v0 + v1;

    int incl = tsum;
#pragma unroll
    for (int off = 1; off < 32; off <<= 1) {
        int n = __shfl_up_sync(0xffffffffu, incl, off);
        if (lane >= off) incl += n;
    }
    const int excl = incl - tsum;

    __shared__ int warpsums[32];
    if (lane == 31) warpsums[wid] = incl;
    __syncthreads();

    if (wid == 0) {
        int w = warpsums[lane];
        int wi = w;
#pragma unroll
        for (int off = 1; off < 32; off <<= 1) {
            int n = __shfl_up_sync(0xffffffffu, wi, off);
            if (lane >= off) wi += n;
        }
        warpsums[lane] = wi - w;
    }
    __syncthreads();

    // global row of first covered position for token idx0: b*S + 1 + start
    const int gbase = b * S + 1 + warpsums[wid] + excl;
    if (idx0 + 1 < T) {
        int2 d;
        d.x = gbase        | (v0 << 20);
        d.y = (gbase + v0) | (v1 << 20);
        *(int2*)(g_desc + (size_t)b * T + idx0) = d;
    } else if (idx0 < T) {
        g_desc[(size_t)b * T + idx0] = gbase | (v0 << 20);
    }
}

// ---------------------------------------------------------------------------
// Kernel 2: HALF a token per warp. Each lane handles 3 float4 (48B);
// 64 lanes (2 warps) cover the 768-float row. One index load per warp,
// no division/multiply on the critical path: descriptor carries the
// global source row directly.
// ---------------------------------------------------------------------------
__global__ void __launch_bounds__(256) pool_kernel(
    const float* __restrict__ hs,      // [B, S, H]
    float*       __restrict__ out)     // [B, T, H]
{
    const int gwarp = (blockIdx.x * blockDim.x + threadIdx.x) >> 5;
    const int lane  = threadIdx.x & 31;
    const int tok   = gwarp >> 1;            // token index
    const int half  = gwarp & 1;             // which half of the row

    const int desc  = __ldg(g_desc + tok);
    const int row0  = desc & 0xFFFFF;        // global source row
    const int len   = desc >> 20;

    const int f4off = half * 96 + lane;      // 96 float4 per half-row

    float4* dst = (float4*)(out + (size_t)tok * H);

    if (len == 0) {
        const float4 z = make_float4(0.f, 0.f, 0.f, 0.f);
#pragma unroll
        for (int k = 0; k < 3; k++) dst[f4off + 32 * k] = z;
        return;
    }

    const float4* src0 = (const float4*)(hs + (size_t)row0 * H);

    float4 acc[3];
#pragma unroll
    for (int k = 0; k < 3; k++) acc[k] = src0[f4off + 32 * k];

    if (len == 2) {
        const float4* src1 = src0 + (H / 4);
#pragma unroll
        for (int k = 0; k < 3; k++) {
            float4 v = src1[f4off + 32 * k];
            acc[k].x = (acc[k].x + v.x) * 0.5f;
            acc[k].y = (acc[k].y + v.y) * 0.5f;
            acc[k].z = (acc[k].z + v.z) * 0.5f;
            acc[k].w = (acc[k].w + v.w) * 0.5f;
        }
    }

#pragma unroll
    for (int k = 0; k < 3; k++) dst[f4off + 32 * k] = acc[k];
}

// ---------------------------------------------------------------------------
extern "C" void kernel_launch(void* const* d_in, const int* in_sizes, int n_in,
                              void* d_out, int out_size)
{
    const float* hs   = (const float*)d_in[0];   // [B,S,H] fp32
    const int*   lens = (const int*)d_in[1];     // [B,T] int32
    float*       out  = (float*)d_out;           // [B,T,H] fp32

    (void)in_sizes; (void)n_in; (void)out_size;

    scan_kernel<<<B, 1024>>>(lens);

    // two warps per token: B*T*2 warps, 8 warps (256 threads) per block
    const int n_warps = B * T * 2;               // 64000
    const int blocks  = n_warps / 8;             // 8000 (exact, no tail CTA)
    pool_kernel<<<blocks, 256>>>(hs, out);
}

// round 13
// speedup vs baseline: 1.0308x; 1.0069x over previous
#include <cuda_runtime.h>
#include <cuda_bf16.h>
#include <cstdint>

// Problem constants
#define B 16
#define S 4096
#define H 768
#define T 2000

#define POOL_CTAS 8000          // B*T*2 half-tokens / 8 warps per CTA
#define GRID (B + POOL_CTAS)    // 16 scan CTAs + 8000 pool CTAs
#define CTAS_PER_BATCH (POOL_CTAS / B)   // 500

// Packed per-token descriptor: (global source row0) | (len << 20).
// row0 = b*S + 1 + start <= 15*4096 + 4001 < 2^20. len in {0,1,2}.
__device__ int g_desc[B * T];
// Per-batch ready flags / exit counters, padded to separate 128B lines.
// Both provably return to 0 at the end of every launch (replay-safe).
__device__ int g_flag[B * 32];
__device__ int g_cnt[B * 32];

// ---------------------------------------------------------------------------
// Single launch. CTAs 0..B-1: scan one batch (256 thr x 8 elems, shuffle
// scan), publish packed descriptors + release flag, retire. CTAs B..: exact
// R5-shape pool (half-token per warp, 3 float4/lane), gated per-batch.
// All cross-CTA data reads go through L2 (__ldcg) -- NEVER the non-coherent
// __ldg path for data written within this launch.
// ---------------------------------------------------------------------------
__global__ void __launch_bounds__(256, 8) fused_kernel(
    const float* __restrict__ hs,      // [B, S, H]
    const int*   __restrict__ lens,    // [B, T]
    float*       __restrict__ out)     // [B, T, H]
{
    const int cta  = blockIdx.x;
    const int tid  = threadIdx.x;
    const int lane = tid & 31;
    const int wid  = tid >> 5;

    if (cta < B) {
        // ==== Scan duty: batch = cta ====
        const int* L = lens + (size_t)cta * T;
        const int idx0 = tid * 8;

        int v[8];
        if (idx0 + 8 <= T) {
            int4 a = *(const int4*)(L + idx0);
            int4 c = *(const int4*)(L + idx0 + 4);
            v[0] = a.x; v[1] = a.y; v[2] = a.z; v[3] = a.w;
            v[4] = c.x; v[5] = c.y; v[6] = c.z; v[7] = c.w;
        } else {
#pragma unroll
            for (int i = 0; i < 8; i++) v[i] = (idx0 + i < T) ? L[idx0 + i] : 0;
        }

        int pre[8], s = 0;
#pragma unroll
        for (int i = 0; i < 8; i++) { pre[i] = s; s += v[i]; }

        int incl = s;
#pragma unroll
        for (int off = 1; off < 32; off <<= 1) {
            int n = __shfl_up_sync(0xffffffffu, incl, off);
            if (lane >= off) incl += n;
        }
        const int excl = incl - s;

        __shared__ int wsums[8];
        if (lane == 31) wsums[wid] = incl;
        __syncthreads();
        if (wid == 0) {
            int w = (lane < 8) ? wsums[lane] : 0;
            int wi = w;
#pragma unroll
            for (int off = 1; off < 8; off <<= 1) {
                int n = __shfl_up_sync(0xffffffffu, wi, off);
                if (lane >= off) wi += n;
            }
            if (lane < 8) wsums[lane] = wi - w;   // exclusive
        }
        __syncthreads();

        // global source row of first covered position: b*S + 1 + start
        const int base = cta * S + 1 + wsums[wid] + excl;
        if (idx0 + 8 <= T) {
            int4 d0, d1;
            d0.x = (base + pre[0]) | (v[0] << 20);
            d0.y = (base + pre[1]) | (v[1] << 20);
            d0.z = (base + pre[2]) | (v[2] << 20);
            d0.w = (base + pre[3]) | (v[3] << 20);
            d1.x = (base + pre[4]) | (v[4] << 20);
            d1.y = (base + pre[5]) | (v[5] << 20);
            d1.z = (base + pre[6]) | (v[6] << 20);
            d1.w = (base + pre[7]) | (v[7] << 20);
            *(int4*)(g_desc + (size_t)cta * T + idx0)     = d0;
            *(int4*)(g_desc + (size_t)cta * T + idx0 + 4) = d1;
        } else {
#pragma unroll
            for (int i = 0; i < 8; i++)
                if (idx0 + i < T)
                    g_desc[(size_t)cta * T + idx0 + i] = (base + pre[i]) | (v[i] << 20);
        }

        // Release: make all desc writes device-visible, then set the flag.
        __threadfence();
        __syncthreads();
        if (tid == 0) atomicExch(&g_flag[cta * 32], 1);
        return;
    }

    // ==== Pool duty (exact R5 shape) ====
    const int pcta  = cta - B;
    const int gwarp = pcta * 8 + wid;
    const int tok   = gwarp >> 1;            // token index
    const int half  = gwarp & 1;

    // Gate on this batch's descriptors (flag read via L2).
    if (tid == 0) {
        const int b = (pcta * 4) / T;        // constant division -> mul/shift
        while (__ldcg(&g_flag[b * 32]) == 0) __nanosleep(64);
        // Replay-safe reset: the 500th batch CTA to pass the gate clears
        // counter+flag (all consumers of this batch have passed by then).
        const int old = atomicAdd(&g_cnt[b * 32], 1);
        if (old == CTAS_PER_BATCH - 1) {
            atomicExch(&g_cnt[b * 32], 0);
            atomicExch(&g_flag[b * 32], 0);
        }
    }
    __syncthreads();

    const int desc  = __ldcg(g_desc + tok);  // L2 read: coherent with scan writes
    const int row0  = desc & 0xFFFFF;        // global source row
    const int len   = desc >> 20;

    const int f4off = half * 96 + lane;      // 96 float4 per half-row
    float4* dst = (float4*)(out + (size_t)tok * H);

    if (len == 0) {
        const float4 z = make_float4(0.f, 0.f, 0.f, 0.f);
#pragma unroll
        for (int k = 0; k < 3; k++) dst[f4off + 32 * k] = z;
        return;
    }

    const float4* src0 = (const float4*)(hs + (size_t)row0 * H);

    float4 acc[3];
#pragma unroll
    for (int k = 0; k < 3; k++) acc[k] = src0[f4off + 32 * k];

    if (len == 2) {
        const float4* src1 = src0 + (H / 4);
#pragma unroll
        for (int k = 0; k < 3; k++) {
            float4 v = src1[f4off + 32 * k];
            acc[k].x = (acc[k].x + v.x) * 0.5f;
            acc[k].y = (acc[k].y + v.y) * 0.5f;
            acc[k].z = (acc[k].z + v.z) * 0.5f;
            acc[k].w = (acc[k].w + v.w) * 0.5f;
        }
    }

#pragma unroll
    for (int k = 0; k < 3; k++) dst[f4off + 32 * k] = acc[k];
}

// ---------------------------------------------------------------------------
extern "C" void kernel_launch(void* const* d_in, const int* in_sizes, int n_in,
                              void* d_out, int out_size)
{
    const float* hs   = (const float*)d_in[0];   // [B,S,H] fp32
    const int*   lens = (const int*)d_in[1];     // [B,T] int32
    float*       out  = (float*)d_out;           // [B,T,H] fp32

    (void)in_sizes; (void)n_in; (void)out_size;

    fused_kernel<<<GRID, 256>>>(hs, lens, out);
}

// round 14
// speedup vs baseline: 1.0407x; 1.0095x over previous
#include <cuda_runtime.h>
#include <cuda_bf16.h>
#include <cstdint>

// Problem constants
#define B 16
#define S 4096
#define H 768
#define T 2000

#define POOL_CTAS 8000          // B*T*2 half-tokens / 8 warps per CTA
#define GRID (B + POOL_CTAS)    // 16 scan CTAs + 8000 pool CTAs
#define CTAS_PER_BATCH (POOL_CTAS / B)   // 500

// Packed per-token descriptor: (global source row0) | (len << 20).
// row0 = b*S + 1 + start <= 15*4096 + 4001 < 2^20. len in {0,1,2}.
__device__ int g_desc[B * T];
// Per-batch ready flags / exit counters, padded to separate 128B lines.
// Both provably return to 0 at the end of every launch (replay-safe).
__device__ int g_flag[B * 32];
__device__ int g_cnt[B * 32];

// ---------------------------------------------------------------------------
// Single launch. CTAs 0..B-1: scan one batch, publish packed descriptors +
// release flag, retire. CTAs B..: R5-shape pool (half-token per warp,
// 3 float4/lane), gated per-batch. Replay-reset counters are incremented
// AFTER pooling (off the critical path; no barrier after them).
// ---------------------------------------------------------------------------
__global__ void __launch_bounds__(256, 8) fused_kernel(
    const float* __restrict__ hs,      // [B, S, H]
    const int*   __restrict__ lens,    // [B, T]
    float*       __restrict__ out)     // [B, T, H]
{
    const int cta  = blockIdx.x;
    const int tid  = threadIdx.x;
    const int lane = tid & 31;
    const int wid  = tid >> 5;

    if (cta < B) {
        // ==== Scan duty: batch = cta ====
        const int* L = lens + (size_t)cta * T;
        const int idx0 = tid * 8;

        int v[8];
        if (idx0 + 8 <= T) {
            int4 a = *(const int4*)(L + idx0);
            int4 c = *(const int4*)(L + idx0 + 4);
            v[0] = a.x; v[1] = a.y; v[2] = a.z; v[3] = a.w;
            v[4] = c.x; v[5] = c.y; v[6] = c.z; v[7] = c.w;
        } else {
#pragma unroll
            for (int i = 0; i < 8; i++) v[i] = (idx0 + i < T) ? L[idx0 + i] : 0;
        }

        int pre[8], s = 0;
#pragma unroll
        for (int i = 0; i < 8; i++) { pre[i] = s; s += v[i]; }

        int incl = s;
#pragma unroll
        for (int off = 1; off < 32; off <<= 1) {
            int n = __shfl_up_sync(0xffffffffu, incl, off);
            if (lane >= off) incl += n;
        }
        const int excl = incl - s;

        __shared__ int wsums[8];
        if (lane == 31) wsums[wid] = incl;
        __syncthreads();
        if (wid == 0) {
            int w = (lane < 8) ? wsums[lane] : 0;
            int wi = w;
#pragma unroll
            for (int off = 1; off < 8; off <<= 1) {
                int n = __shfl_up_sync(0xffffffffu, wi, off);
                if (lane >= off) wi += n;
            }
            if (lane < 8) wsums[lane] = wi - w;   // exclusive
        }
        __syncthreads();

        // global source row of first covered position: b*S + 1 + start
        const int base = cta * S + 1 + wsums[wid] + excl;
        if (idx0 + 8 <= T) {
            int4 d0, d1;
            d0.x = (base + pre[0]) | (v[0] << 20);
            d0.y = (base + pre[1]) | (v[1] << 20);
            d0.z = (base + pre[2]) | (v[2] << 20);
            d0.w = (base + pre[3]) | (v[3] << 20);
            d1.x = (base + pre[4]) | (v[4] << 20);
            d1.y = (base + pre[5]) | (v[5] << 20);
            d1.z = (base + pre[6]) | (v[6] << 20);
            d1.w = (base + pre[7]) | (v[7] << 20);
            *(int4*)(g_desc + (size_t)cta * T + idx0)     = d0;
            *(int4*)(g_desc + (size_t)cta * T + idx0 + 4) = d1;
        } else {
#pragma unroll
            for (int i = 0; i < 8; i++)
                if (idx0 + i < T)
                    g_desc[(size_t)cta * T + idx0 + i] = (base + pre[i]) | (v[i] << 20);
        }

        // Release: make all desc writes device-visible, then set the flag.
        __threadfence();
        __syncthreads();
        if (tid == 0) atomicExch(&g_flag[cta * 32], 1);
        return;
    }

    // ==== Pool duty (R5 shape) ====
    const int pcta  = cta - B;
    const int gwarp = pcta * 8 + wid;
    const int tok   = gwarp >> 1;            // token index
    const int half  = gwarp & 1;
    const int b     = (pcta * 4) / T;        // constant division -> mul/shift

    // Gate on this batch's descriptors (flag read via L2). No atomics here.
    if (tid == 0) {
        while (__ldcg(&g_flag[b * 32]) == 0) __nanosleep(64);
    }
    __syncthreads();

    const int desc  = __ldcg(g_desc + tok);  // L2 read: coherent with scan writes
    const int row0  = desc & 0xFFFFF;        // global source row
    const int len   = desc >> 20;

    const int f4off = half * 96 + lane;      // 96 float4 per half-row
    float4* dst = (float4*)(out + (size_t)tok * H);

    if (len == 0) {
        const float4 z = make_float4(0.f, 0.f, 0.f, 0.f);
#pragma unroll
        for (int k = 0; k < 3; k++) dst[f4off + 32 * k] = z;
    } else {
        const float4* src0 = (const float4*)(hs + (size_t)row0 * H);

        float4 acc[3];
#pragma unroll
        for (int k = 0; k < 3; k++) acc[k] = src0[f4off + 32 * k];

        if (len == 2) {
            const float4* src1 = src0 + (H / 4);
#pragma unroll
            for (int k = 0; k < 3; k++) {
                float4 v = src1[f4off + 32 * k];
                acc[k].x = (acc[k].x + v.x) * 0.5f;
                acc[k].y = (acc[k].y + v.y) * 0.5f;
                acc[k].z = (acc[k].z + v.z) * 0.5f;
                acc[k].w = (acc[k].w + v.w) * 0.5f;
            }
        }

#pragma unroll
        for (int k = 0; k < 3; k++) dst[f4off + 32 * k] = acc[k];
    }

    // ==== Replay-reset, OFF the critical path: after pooling, no barrier.
    // The 500th incrementer for this batch has proof all batch CTAs passed
    // the gate, so clearing flag+cnt is safe; end-state is zeros every launch.
    if (tid == 0) {
        const int old = atomicAdd(&g_cnt[b * 32], 1);
        if (old == CTAS_PER_BATCH - 1) {
            atomicExch(&g_cnt[b * 32], 0);
            atomicExch(&g_flag[b * 32], 0);
        }
    }
}

// ---------------------------------------------------------------------------
extern "C" void kernel_launch(void* const* d_in, const int* in_sizes, int n_in,
                              void* d_out, int out_size)
{
    const float* hs   = (const float*)d_in[0];   // [B,S,H] fp32
    const int*   lens = (const int*)d_in[1];     // [B,T] int32
    float*       out  = (float*)d_out;           // [B,T,H] fp32

    (void)in_sizes; (void)n_in; (void)out_size;

    fused_kernel<<<GRID, 256>>>(hs, lens, out);
}